// round 16
// baseline (speedup 1.0000x reference)
#include <cuda_runtime.h>
#include <cuda_bf16.h>
#include <stdint.h>
#include <math.h>

// Problem constants (fixed by the reference)
#define BATCH 8
#define CH    512
#define HW    1024       // 32*32 spatial
#define NG    32
#define CPG   16
#define GRP_ELEMS (CPG*HW)   // 16384

typedef __nv_bfloat16 bf16;

// ---------------- scratch (static device globals; no allocation) -------------
__device__ bf16  g_xnT   [BATCH * HW * CH];    // xn^T [b][pix][c]
__device__ bf16  g_zT    [BATCH * HW * CH];    // Z^T  [b][j][c']   (Wqk . xn)^T
__device__ bf16  g_uPV   [BATCH * CH * HW];    // U    [b][co][j]   (Wpv . xn)
__device__ float g_attn  [BATCH * HW * HW];    // scores fp32 [b][i][j]
__device__ bf16  g_attnbf[BATCH * HW * HW];    // softmaxed, bf16
__device__ bf16  g_wqT   [CH * CH];            // Wq^T bf16
__device__ bf16  g_wkT   [CH * CH];            // Wk^T bf16
__device__ bf16  g_wvT   [CH * CH];            // Wv^T bf16
__device__ bf16  g_pbf   [CH * CH];            // proj_w bf16
__device__ bf16  g_wqk   [CH * CH];            // Wq^T.Wk bf16
__device__ bf16  g_wpv   [CH * CH];            // P.Wv bf16
__device__ float g_uvec  [CH];                 // Wk^T . bq
__device__ float g_svec  [BATCH * HW];         // per-column softmax correction
__device__ float g_btot  [CH];                 // proj_b + P.bv

// ---------------- helpers -----------------------------------------------------
__device__ __forceinline__ uint32_t packbf(float x, float y) {
    __nv_bfloat162 h = __float22bfloat162_rn(make_float2(x, y));
    return *(uint32_t*)&h;
}
__device__ __forceinline__ uint32_t smem_u32(const void* p) {
    return (uint32_t)__cvta_generic_to_shared(p);
}
#define CP_ASYNC16(dst, src) \
    asm volatile("cp.async.cg.shared.global [%0], [%1], 16;\n" :: "r"(dst), "l"(src))
#define CP_COMMIT()  asm volatile("cp.async.commit_group;\n" ::)
#define CP_WAIT1()   asm volatile("cp.async.wait_group 1;\n" ::)

// ---------------- weight conversion / transpose ------------------------------
__global__ void tobf16_kernel(const float* __restrict__ in, bf16* __restrict__ out, int n4)
{
    int i = blockIdx.x * blockDim.x + threadIdx.x;
    if (i < n4) {
        float4 v = ((const float4*)in)[i];
        uint2 o = make_uint2(packbf(v.x, v.y), packbf(v.z, v.w));
        ((uint2*)out)[i] = o;
    }
}

// 512x512 fp32 -> bf16 transposed
__global__ __launch_bounds__(256)
void transpose_bf16_kernel(const float* __restrict__ in, bf16* __restrict__ out)
{
    __shared__ float t[32][33];
    const int tx = threadIdx.x & 31, ty = threadIdx.x >> 5;   // 32 x 8
    const int x  = blockIdx.x * 32 + tx;
    const int y0 = blockIdx.y * 32;
    #pragma unroll
    for (int j = ty; j < 32; j += 8)
        t[j][tx] = in[(size_t)(y0 + j) * CH + x];
    __syncthreads();
    const int ox  = blockIdx.y * 32 + tx;
    const int oy0 = blockIdx.x * 32;
    #pragma unroll
    for (int j = ty; j < 32; j += 8)
        out[(size_t)(oy0 + j) * CH + ox] = __float2bfloat16(t[tx][j]);
}

// u[c'] = sum_o Wk[o][c'] * bq[o]
__global__ void compute_u_kernel(const float* __restrict__ qkv_w,
                                 const float* __restrict__ qkv_b,
                                 float* __restrict__ u)
{
    int c1 = blockIdx.x * 256 + threadIdx.x;
    float acc = 0.f;
    for (int o = 0; o < CH; o++)
        acc += qkv_w[(size_t)(CH + o) * CH + c1] * qkv_b[o];
    u[c1] = acc;
}

// btot[co] = proj_b[co] + sum_c P[co][c] * bv[c]
__global__ void compute_btot_kernel(const float* __restrict__ proj_w,
                                    const float* __restrict__ proj_b,
                                    const float* __restrict__ qkv_b,
                                    float* __restrict__ btot)
{
    int co = blockIdx.x * 8 + (threadIdx.x >> 5);
    int lane = threadIdx.x & 31;
    const float* bv = qkv_b + 2 * CH;
    float acc = 0.f;
    for (int c = lane; c < CH; c += 32)
        acc += proj_w[(size_t)co * CH + c] * bv[c];
    #pragma unroll
    for (int o = 16; o > 0; o >>= 1) acc += __shfl_xor_sync(0xffffffffu, acc, o);
    if (lane == 0) btot[co] = proj_b[co] + acc;
}

// s[b*HW+j] = sum_c u[c] * xnT[b][j][c]
__global__ void compute_s_kernel(const bf16* __restrict__ xnT,
                                 const float* __restrict__ u,
                                 float* __restrict__ s)
{
    int gw = blockIdx.x * 8 + (threadIdx.x >> 5);   // 0..8191
    int lane = threadIdx.x & 31;
    const bf16* xp = xnT + (size_t)gw * CH;
    float acc = 0.f;
    for (int c = lane; c < CH; c += 32)
        acc += __bfloat162float(xp[c]) * u[c];
    #pragma unroll
    for (int o = 16; o > 0; o >>= 1) acc += __shfl_xor_sync(0xffffffffu, acc, o);
    if (lane == 0) s[gw] = acc;
}

// ---------------- GroupNorm (writes transposed bf16 xnT) ---------------------
__global__ __launch_bounds__(256)
void groupnorm_t_kernel(const float* __restrict__ x,
                        const float* __restrict__ w,
                        const float* __restrict__ bias,
                        bf16* __restrict__ xnT)
{
    const int bg = blockIdx.x;
    const int b  = bg / NG;
    const int g  = bg % NG;
    const float* xp = x + ((size_t)b * CH + (size_t)g * CPG) * HW;

    const int tid = threadIdx.x;
    float sum = 0.f, sq = 0.f;
    for (int i = tid; i < GRP_ELEMS; i += 256) {
        float v = xp[i];
        sum += v; sq += v * v;
    }
    __shared__ float ssum[8], ssq[8];
    int lane = tid & 31, wid = tid >> 5;
    #pragma unroll
    for (int o = 16; o > 0; o >>= 1) {
        sum += __shfl_xor_sync(0xffffffffu, sum, o);
        sq  += __shfl_xor_sync(0xffffffffu, sq,  o);
    }
    if (lane == 0) { ssum[wid] = sum; ssq[wid] = sq; }
    __syncthreads();
    if (wid == 0) {
        sum = ssum[lane & 7];
        sq  = ssq [lane & 7];
        #pragma unroll
        for (int o = 4; o > 0; o >>= 1) {
            sum += __shfl_xor_sync(0xffffffffu, sum, o);
            sq  += __shfl_xor_sync(0xffffffffu, sq,  o);
        }
        if (lane == 0) { ssum[0] = sum; ssq[0] = sq; }
    }
    __syncthreads();
    const float inv_n = 1.f / (float)GRP_ELEMS;
    const float mean  = ssum[0] * inv_n;
    const float var   = ssq[0] * inv_n - mean * mean;
    const float rstd  = rsqrtf(var + 1e-5f);

    __shared__ float tile[CPG][64 + 1];
    for (int pt = 0; pt < 16; pt++) {
        __syncthreads();
        #pragma unroll
        for (int j = 0; j < 4; j++) {
            int e = tid + j * 256;
            int c = e >> 6, p = e & 63;
            float v = xp[c * HW + pt * 64 + p];
            tile[c][p] = (v - mean) * rstd * w[g * CPG + c] + bias[g * CPG + c];
        }
        __syncthreads();
        int p = tid >> 2, cq = tid & 3;
        uint2 o = make_uint2(packbf(tile[cq * 4 + 0][p], tile[cq * 4 + 1][p]),
                             packbf(tile[cq * 4 + 2][p], tile[cq * 4 + 3][p]));
        *(uint2*)&xnT[((size_t)b * HW + pt * 64 + p) * CH + g * CPG + cq * 4] = o;
    }
}

// ---------------- pipelined bf16 tensor-core GEMM ----------------------------
// C[b][m][n] = alpha * sum_k A[m][k]*B[n][k]  (+biasN[n]) (+res)
// OUT_T: writes C transposed as fp32 [n][m] (ldt), with res read [n][m] and
// biasN[n] — used by the final gemm to emit d_out directly (smem-staged,
// coalesced). Tiles BM=BN=128, BK=64; 8 warps (2M x 4N), mma.m16n8k16,
// 3-stage cp.async ring, one __syncthreads per 64-k iter (R9 mainloop).
#define GS 3
#define G_LDS 72                      // BK + 8 pad
#define G_STAGE_E (128 * G_LDS)
#define G_SMEM (2 * GS * G_STAGE_E * 2)   // 110592 bytes

template<bool BIAS_N, bool HAS_RES, bool OUT_BF, bool OUT_T>
__global__ __launch_bounds__(256, 2)
void gemm_pipe(const bf16* __restrict__ A, const bf16* __restrict__ B,
               const float* __restrict__ biasN,
               const float* __restrict__ res, void* __restrict__ Cp,
               int N, int K, int lda, int ldb, int ldt,
               size_t strideA, size_t strideB, size_t strideC, size_t strideRes,
               float alpha)
{
    constexpr int BK = 64;
    extern __shared__ __align__(16) bf16 sm[];
    bf16* As = sm;
    bf16* Bs = sm + GS * G_STAGE_E;

    const int tid  = threadIdx.x;
    const int lane = tid & 31;
    const int warp = tid >> 5;
    const int wm = warp & 1;
    const int wn = warp >> 1;
    const int g   = lane >> 2;
    const int tg2 = (lane & 3) * 2;

    const int batch = blockIdx.z;
    const int m0 = blockIdx.y * 128;
    const int n0 = blockIdx.x * 128;

    const int srow = tid >> 3;
    const int sch  = tid & 7;
    const bf16* Ag = A + batch * strideA + (size_t)(m0 + srow) * lda + sch * 8;
    const bf16* Bg = B + batch * strideB + (size_t)(n0 + srow) * ldb + sch * 8;
    const uint32_t aB = smem_u32(&As[srow * G_LDS + sch * 8]);
    const uint32_t bB = smem_u32(&Bs[srow * G_LDS + sch * 8]);
    constexpr uint32_t STG = G_STAGE_E * 2;
    constexpr uint32_t R32 = 32 * G_LDS * 2;

    const int nk = K / BK;

    #pragma unroll
    for (int s = 0; s < GS - 1; s++) {
        const bf16* Ak = Ag + s * BK;
        const bf16* Bk = Bg + s * BK;
        #pragma unroll
        for (int p = 0; p < 4; p++) {
            CP_ASYNC16(aB + s * STG + p * R32, Ak + (size_t)(32 * p) * lda);
            CP_ASYNC16(bB + s * STG + p * R32, Bk + (size_t)(32 * p) * ldb);
        }
        CP_COMMIT();
    }

    float acc[4][4][4];
    #pragma unroll
    for (int i = 0; i < 4; i++)
        #pragma unroll
        for (int j = 0; j < 4; j++)
            #pragma unroll
            for (int r = 0; r < 4; r++) acc[i][j][r] = 0.f;

    const int arow = (lane & 15);
    const int acol = ((lane >> 4) & 1) * 8;
    const int brow = (lane & 7) + ((lane >> 4) << 3);
    const int bcol = ((lane >> 3) & 1) * 8;

    for (int kt = 0; kt < nk; kt++) {
        CP_WAIT1();
        __syncthreads();

        {
            const int pf = kt + GS - 1;
            if (pf < nk) {
                const int ps = pf % GS;
                const bf16* Ak = Ag + pf * BK;
                const bf16* Bk = Bg + pf * BK;
                #pragma unroll
                for (int p = 0; p < 4; p++) {
                    CP_ASYNC16(aB + ps * STG + p * R32, Ak + (size_t)(32 * p) * lda);
                    CP_ASYNC16(bB + ps * STG + p * R32, Bk + (size_t)(32 * p) * ldb);
                }
            }
            CP_COMMIT();
        }

        const int buf = kt % GS;
        const bf16* Ab = As + buf * G_STAGE_E;
        const bf16* Bb = Bs + buf * G_STAGE_E;

        #pragma unroll
        for (int ks = 0; ks < 4; ks++) {
            const int kb = ks * 16;
            uint32_t a[4][4];
            #pragma unroll
            for (int mt = 0; mt < 4; mt++) {
                uint32_t addr = smem_u32(&Ab[(wm * 64 + mt * 16 + arow) * G_LDS + kb + acol]);
                asm volatile("ldmatrix.sync.aligned.m8n8.x4.shared.b16 {%0,%1,%2,%3}, [%4];\n"
                             : "=r"(a[mt][0]), "=r"(a[mt][1]), "=r"(a[mt][2]), "=r"(a[mt][3])
                             : "r"(addr));
            }
            uint32_t b[4][2];
            #pragma unroll
            for (int np = 0; np < 2; np++) {
                uint32_t addr = smem_u32(&Bb[(wn * 32 + np * 16 + brow) * G_LDS + kb + bcol]);
                uint32_t r0, r1, r2, r3;
                asm volatile("ldmatrix.sync.aligned.m8n8.x4.shared.b16 {%0,%1,%2,%3}, [%4];\n"
                             : "=r"(r0), "=r"(r1), "=r"(r2), "=r"(r3)
                             : "r"(addr));
                b[np * 2 + 0][0] = r0; b[np * 2 + 0][1] = r1;
                b[np * 2 + 1][0] = r2; b[np * 2 + 1][1] = r3;
            }
            #pragma unroll
            for (int mt = 0; mt < 4; mt++)
                #pragma unroll
                for (int nt = 0; nt < 4; nt++) {
                    asm volatile(
                        "mma.sync.aligned.m16n8k16.row.col.f32.bf16.bf16.f32 "
                        "{%0,%1,%2,%3}, {%4,%5,%6,%7}, {%8,%9}, {%0,%1,%2,%3};\n"
                        : "+f"(acc[mt][nt][0]), "+f"(acc[mt][nt][1]),
                          "+f"(acc[mt][nt][2]), "+f"(acc[mt][nt][3])
                        : "r"(a[mt][0]), "r"(a[mt][1]), "r"(a[mt][2]), "r"(a[mt][3]),
                          "r"(b[nt][0]), "r"(b[nt][1]));
                }
        }
    }

    if (OUT_T) {
        // stage tile in smem (col-major [n_local][132]) then coalesced fp32 out
        constexpr int TP = 132;
        float* Ct = (float*)sm;
        __syncthreads();
        #pragma unroll
        for (int mt = 0; mt < 4; mt++) {
            int ml = wm * 64 + mt * 16 + g;
            #pragma unroll
            for (int nt = 0; nt < 4; nt++) {
                int nl = wn * 32 + nt * 8 + tg2;
                Ct[nl * TP + ml]           = alpha * acc[mt][nt][0];
                Ct[(nl + 1) * TP + ml]     = alpha * acc[mt][nt][1];
                Ct[nl * TP + ml + 8]       = alpha * acc[mt][nt][2];
                Ct[(nl + 1) * TP + ml + 8] = alpha * acc[mt][nt][3];
            }
        }
        __syncthreads();
        float* Cb = (float*)Cp + batch * strideC;
        const float* Rb = res + batch * strideRes;
        #pragma unroll
        for (int it = 0; it < 16; it++) {
            int idx = tid + it * 256;         // 0..4095
            int nl = idx >> 5;                // col 0..127
            int mq = (idx & 31) * 4;          // row base
            int col = n0 + nl;
            int row = m0 + mq;
            float4 c;
            c.x = Ct[nl * TP + mq + 0];
            c.y = Ct[nl * TP + mq + 1];
            c.z = Ct[nl * TP + mq + 2];
            c.w = Ct[nl * TP + mq + 3];
            float bn = BIAS_N ? biasN[col] : 0.f;
            if (HAS_RES) {
                float4 r = *(const float4*)&Rb[(size_t)col * ldt + row];
                c.x += r.x; c.y += r.y; c.z += r.z; c.w += r.w;
            }
            c.x += bn; c.y += bn; c.z += bn; c.w += bn;
            *(float4*)&Cb[(size_t)col * ldt + row] = c;
        }
        return;
    }

    // ---- standard epilogue
    #pragma unroll
    for (int mt = 0; mt < 4; mt++) {
        int row = m0 + wm * 64 + mt * 16 + g;
        #pragma unroll
        for (int nt = 0; nt < 4; nt++) {
            int col = n0 + wn * 32 + nt * 8 + tg2;
            float2 v0, v1;
            v0.x = alpha * acc[mt][nt][0];
            v0.y = alpha * acc[mt][nt][1];
            v1.x = alpha * acc[mt][nt][2];
            v1.y = alpha * acc[mt][nt][3];
            if (BIAS_N) {
                float2 bn = *(const float2*)&biasN[col];
                v0.x += bn.x; v0.y += bn.y;
                v1.x += bn.x; v1.y += bn.y;
            }
            if (OUT_BF) {
                bf16* Cb = (bf16*)Cp + batch * strideC;
                *(uint32_t*)&Cb[(size_t)row * N + col]       = packbf(v0.x, v0.y);
                *(uint32_t*)&Cb[(size_t)(row + 8) * N + col] = packbf(v1.x, v1.y);
            } else {
                float* Cb = (float*)Cp + batch * strideC;
                *(float2*)&Cb[(size_t)row * N + col]       = v0;
                *(float2*)&Cb[(size_t)(row + 8) * N + col] = v1;
            }
        }
    }
}

// ---------------- Row softmax (+ per-column bias correction) ------------------
__global__ __launch_bounds__(256)
void softmax_kernel(const float* __restrict__ attn, bf16* __restrict__ attnbf,
                    const float* __restrict__ s, float scale)
{
    const int warp = threadIdx.x >> 5;
    const int lane = threadIdx.x & 31;
    const size_t row = (size_t)blockIdx.x * 8 + warp;
    const float4* rp = (const float4*)(attn + row * HW);
    const float4* sp = (const float4*)(s + (row >> 10) * HW);
    uint2* op = (uint2*)(attnbf + row * HW);

    float4 v[8];
    float mx = -3.4e38f;
    #pragma unroll
    for (int i = 0; i < 8; i++) {
        v[i] = rp[lane + i * 32];
        float4 s4 = sp[lane + i * 32];
        v[i].x += scale * s4.x; v[i].y += scale * s4.y;
        v[i].z += scale * s4.z; v[i].w += scale * s4.w;
        mx = fmaxf(mx, fmaxf(fmaxf(v[i].x, v[i].y), fmaxf(v[i].z, v[i].w)));
    }
    #pragma unroll
    for (int o = 16; o > 0; o >>= 1) mx = fmaxf(mx, __shfl_xor_sync(0xffffffffu, mx, o));

    float sum = 0.f;
    #pragma unroll
    for (int i = 0; i < 8; i++) {
        v[i].x = __expf(v[i].x - mx); v[i].y = __expf(v[i].y - mx);
        v[i].z = __expf(v[i].z - mx); v[i].w = __expf(v[i].w - mx);
        sum += (v[i].x + v[i].y) + (v[i].z + v[i].w);
    }
    #pragma unroll
    for (int o = 16; o > 0; o >>= 1) sum += __shfl_xor_sync(0xffffffffu, sum, o);

    const float inv = 1.f / sum;
    #pragma unroll
    for (int i = 0; i < 8; i++) {
        uint2 o2 = make_uint2(packbf(v[i].x * inv, v[i].y * inv),
                              packbf(v[i].z * inv, v[i].w * inv));
        op[lane + i * 32] = o2;
    }
}

// ---------------- launch ------------------------------------------------------
extern "C" void kernel_launch(void* const* d_in, const int* in_sizes, int n_in,
                              void* d_out, int out_size)
{
    const float* x      = (const float*)d_in[0];
    const float* gn_w   = (const float*)d_in[1];
    const float* gn_b   = (const float*)d_in[2];
    const float* qkv_w  = (const float*)d_in[3];
    const float* qkv_b  = (const float*)d_in[4];
    const float* proj_w = (const float*)d_in[5];
    const float* proj_b = (const float*)d_in[6];
    float* out = (float*)d_out;

    bf16 *xnT, *zT, *uPV, *attnbf, *wqT, *wkT, *wvT, *pbf, *wqk, *wpv;
    float *attn, *uvec, *svec, *btot;
    cudaGetSymbolAddress((void**)&xnT,    g_xnT);
    cudaGetSymbolAddress((void**)&zT,     g_zT);
    cudaGetSymbolAddress((void**)&uPV,    g_uPV);
    cudaGetSymbolAddress((void**)&attn,   g_attn);
    cudaGetSymbolAddress((void**)&attnbf, g_attnbf);
    cudaGetSymbolAddress((void**)&wqT,    g_wqT);
    cudaGetSymbolAddress((void**)&wkT,    g_wkT);
    cudaGetSymbolAddress((void**)&wvT,    g_wvT);
    cudaGetSymbolAddress((void**)&pbf,    g_pbf);
    cudaGetSymbolAddress((void**)&wqk,    g_wqk);
    cudaGetSymbolAddress((void**)&wpv,    g_wpv);
    cudaGetSymbolAddress((void**)&uvec,   g_uvec);
    cudaGetSymbolAddress((void**)&svec,   g_svec);
    cudaGetSymbolAddress((void**)&btot,   g_btot);

    cudaFuncSetAttribute(gemm_pipe<false, false, true,  false>, cudaFuncAttributeMaxDynamicSharedMemorySize, G_SMEM);
    cudaFuncSetAttribute(gemm_pipe<false, false, false, false>, cudaFuncAttributeMaxDynamicSharedMemorySize, G_SMEM);
    cudaFuncSetAttribute(gemm_pipe<true,  true,  false, true >, cudaFuncAttributeMaxDynamicSharedMemorySize, G_SMEM);

    const size_t sNC  = (size_t)HW * CH;
    const size_t sCN  = (size_t)CH * HW;
    const size_t sATT = (size_t)HW * HW;
    const float scale = rsqrtf((float)CH);

    // 0) weight preprocessing
    {
        dim3 tg(16, 16);
        transpose_bf16_kernel<<<tg, 256>>>(qkv_w,                       wqT);
        transpose_bf16_kernel<<<tg, 256>>>(qkv_w + (size_t)CH * CH,     wkT);
        transpose_bf16_kernel<<<tg, 256>>>(qkv_w + (size_t)2 * CH * CH, wvT);
    }
    tobf16_kernel<<<(CH * CH / 4 + 255) / 256, 256>>>(proj_w, pbf, CH * CH / 4);
    compute_u_kernel<<<CH / 256, 256>>>(qkv_w, qkv_b, uvec);
    compute_btot_kernel<<<CH / 8, 256>>>(proj_w, proj_b, qkv_b, btot);

    // Wqk = Wq^T . Wk   (512x512x512)
    gemm_pipe<false, false, true, false><<<dim3(4, 4, 1), 256, G_SMEM>>>(
        wqT, wkT, nullptr, nullptr, wqk,
        CH, CH, CH, CH, 0, 0, 0, 0, 0, 1.0f);
    // Wpv = P . Wv
    gemm_pipe<false, false, true, false><<<dim3(4, 4, 1), 256, G_SMEM>>>(
        pbf, wvT, nullptr, nullptr, wpv,
        CH, CH, CH, CH, 0, 0, 0, 0, 0, 1.0f);

    // 1) GroupNorm -> xnT bf16 [b][pix][c]
    groupnorm_t_kernel<<<BATCH * NG, 256>>>(x, gn_w, gn_b, xnT);

    // 1b) s[b][j] = u . xn_j (Q-bias column correction)
    compute_s_kernel<<<BATCH * HW / 8, 256>>>(xnT, uvec, svec);

    // 2) Z^T[b][j][c'] = sum_c'' Wqk[c'][c''] xnT[j][c'']
    gemm_pipe<false, false, true, false><<<dim3(CH / 128, HW / 128, BATCH), 256, G_SMEM>>>(
        xnT, wqk, nullptr, nullptr, zT,
        CH, CH, CH, CH, 0, sNC, 0, sNC, 0, 1.0f);

    // 3) U[b][co][j] = sum_c Wpv[co][c] xnT[j][c]
    gemm_pipe<false, false, true, false><<<dim3(HW / 128, CH / 128, BATCH), 256, G_SMEM>>>(
        wpv, xnT, nullptr, nullptr, uPV,
        HW, CH, CH, CH, 0, 0, sNC, sCN, 0, 1.0f);

    // 4) S[b][i][j] = scale * sum_c' xnT[i][c'] zT[j][c']   (fp32)
    gemm_pipe<false, false, false, false><<<dim3(HW / 128, HW / 128, BATCH), 256, G_SMEM>>>(
        xnT, zT, nullptr, nullptr, attn,
        HW, CH, CH, CH, 0, sNC, sNC, sATT, 0, scale);

    // 5) softmax rows (+ scale*s[j]) -> bf16
    softmax_kernel<<<BATCH * HW / 8, 256>>>(attn, attnbf, svec, scale);

    // 6) out[b][co][i] = sum_j A[i][j] U[co][j] + x[b][co][i] + btot[co]
    gemm_pipe<true, true, false, true><<<dim3(CH / 128, HW / 128, BATCH), 256, G_SMEM>>>(
        attnbf, uPV, btot, x, out,
        CH, HW, HW, HW, HW, sATT, sCN, sCN, sCN, 1.0f);
}